// round 7
// baseline (speedup 1.0000x reference)
#include <cuda_runtime.h>
#include <cuda_bf16.h>
#include <cstdint>

#define NUM_GRIDS 8

__device__ __forceinline__ float tanh_approx(float x) {
    float y;
    asm("tanh.approx.f32 %0, %1;" : "=f"(y) : "f"(x));
    return y;
}

__device__ __forceinline__ void stg256(float* dst, const float* r) {
    asm volatile(
        "st.global.cs.v8.f32 [%0], {%1,%2,%3,%4,%5,%6,%7,%8};"
        :: "l"(dst),
           "f"(r[0]), "f"(r[1]), "f"(r[2]), "f"(r[3]),
           "f"(r[4]), "f"(r[5]), "f"(r[6]), "f"(r[7])
        : "memory");
}

// One thread per float4 of x (4 elements): 1x LDG.128 in (warp = 512 B
// contiguous), 32 outputs out via 4x STG.256 (warp = 4 KB contiguous).
__global__ __launch_bounds__(256)
void rswaf_kernel(const float4* __restrict__ x,
                  const float4* __restrict__ grid,   // [8] floats = 2 float4
                  const float*  __restrict__ inv_den,
                  float*        __restrict__ out,
                  int n4) {
    const int i = blockIdx.x * blockDim.x + threadIdx.x;
    if (i >= n4) return;

    const float inv = __ldg(inv_den);

    // pre-scale grid by inv: (x-g)*inv = x*inv - g*inv
    const float4 gA = __ldg(grid + 0);
    const float4 gB = __ldg(grid + 1);
    const float gs[NUM_GRIDS] = {gA.x * inv, gA.y * inv, gA.z * inv, gA.w * inv,
                                 gB.x * inv, gB.y * inv, gB.z * inv, gB.w * inv};

    const float4 xv = __ldcs(x + i);
    const float xs[4] = {xv.x * inv, xv.y * inv, xv.z * inv, xv.w * inv};

    float* dst = out + (long long)i * (4 * NUM_GRIDS);

#pragma unroll
    for (int e = 0; e < 4; e++) {
        float r[NUM_GRIDS];
#pragma unroll
        for (int j = 0; j < NUM_GRIDS; j++) {
            const float th = tanh_approx(xs[e] - gs[j]);
            r[j] = 1.0f - th * th;
        }
        stg256(dst + e * NUM_GRIDS, r);
    }
}

extern "C" void kernel_launch(void* const* d_in, const int* in_sizes, int n_in,
                              void* d_out, int out_size) {
    const float* x       = (const float*)d_in[0];   // [16,64,128,128] fp32
    const float* grid    = (const float*)d_in[1];   // [8] fp32
    const float* inv_den = (const float*)d_in[2];   // scalar fp32
    float* out = (float*)d_out;                     // [...,8] fp32

    const int n  = in_sizes[0];        // 16,777,216 (divisible by 4)
    const int n4 = n >> 2;             // 4,194,304 float4s

    const int threads = 256;
    const int blocks  = (n4 + threads - 1) / threads;   // 16384

    rswaf_kernel<<<blocks, threads>>>(
        (const float4*)x, (const float4*)grid, inv_den, out, n4);
}

// round 8
// speedup vs baseline: 1.0181x; 1.0181x over previous
#include <cuda_runtime.h>
#include <cuda_bf16.h>
#include <cstdint>

#define NUM_GRIDS 8

__device__ __forceinline__ float tanh_approx(float x) {
    float y;
    asm("tanh.approx.f32 %0, %1;" : "=f"(y) : "f"(x));
    return y;
}

__device__ __forceinline__ float bump(float xi, float g) {
    const float th = tanh_approx(xi - g);
    return 1.0f - th * th;
}

// Two elements per thread: 1x LDG.64 in (warp = 256 B contiguous),
// 16 outputs out via 2x STG.256 (warp = 2 KB contiguous). All results
// held in named scalars: zero spill risk.
__global__ __launch_bounds__(256)
void rswaf_kernel(const float2* __restrict__ x,
                  const float4* __restrict__ grid,   // [8] floats = 2 float4
                  const float*  __restrict__ inv_den,
                  float*        __restrict__ out,
                  int n2) {
    const int i = blockIdx.x * blockDim.x + threadIdx.x;
    if (i >= n2) return;

    const float inv = __ldg(inv_den);

    // pre-scale grid by inv: (x-g)*inv = x*inv - g*inv
    const float4 gA = __ldg(grid + 0);
    const float4 gB = __ldg(grid + 1);
    const float g0 = gA.x * inv, g1 = gA.y * inv, g2 = gA.z * inv, g3 = gA.w * inv;
    const float g4 = gB.x * inv, g5 = gB.y * inv, g6 = gB.z * inv, g7 = gB.w * inv;

    const float2 xv = __ldcs(x + i);
    const float xa = xv.x * inv;
    const float xb = xv.y * inv;

    const float a0 = bump(xa, g0), a1 = bump(xa, g1), a2 = bump(xa, g2), a3 = bump(xa, g3);
    const float a4 = bump(xa, g4), a5 = bump(xa, g5), a6 = bump(xa, g6), a7 = bump(xa, g7);

    float* dst = out + (long long)i * (2 * NUM_GRIDS);
    asm volatile(
        "st.global.cs.v8.f32 [%0], {%1,%2,%3,%4,%5,%6,%7,%8};"
        :: "l"(dst),
           "f"(a0), "f"(a1), "f"(a2), "f"(a3),
           "f"(a4), "f"(a5), "f"(a6), "f"(a7)
        : "memory");

    const float b0 = bump(xb, g0), b1 = bump(xb, g1), b2 = bump(xb, g2), b3 = bump(xb, g3);
    const float b4 = bump(xb, g4), b5 = bump(xb, g5), b6 = bump(xb, g6), b7 = bump(xb, g7);

    asm volatile(
        "st.global.cs.v8.f32 [%0], {%1,%2,%3,%4,%5,%6,%7,%8};"
        :: "l"(dst + NUM_GRIDS),
           "f"(b0), "f"(b1), "f"(b2), "f"(b3),
           "f"(b4), "f"(b5), "f"(b6), "f"(b7)
        : "memory");
}

extern "C" void kernel_launch(void* const* d_in, const int* in_sizes, int n_in,
                              void* d_out, int out_size) {
    const float* x       = (const float*)d_in[0];   // [16,64,128,128] fp32
    const float* grid    = (const float*)d_in[1];   // [8] fp32
    const float* inv_den = (const float*)d_in[2];   // scalar fp32
    float* out = (float*)d_out;                     // [...,8] fp32

    const int n  = in_sizes[0];        // 16,777,216 (even)
    const int n2 = n >> 1;             // 8,388,608 float2s

    const int threads = 256;
    const int blocks  = (n2 + threads - 1) / threads;   // 32768

    rswaf_kernel<<<blocks, threads>>>(
        (const float2*)x, (const float4*)grid, inv_den, out, n2);
}

// round 9
// speedup vs baseline: 1.2683x; 1.2457x over previous
#include <cuda_runtime.h>
#include <cuda_bf16.h>
#include <cstdint>

#define NUM_GRIDS 8

__device__ __forceinline__ float tanh_approx(float x) {
    float y;
    asm("tanh.approx.f32 %0, %1;" : "=f"(y) : "f"(x));
    return y;
}

__device__ __forceinline__ float bump(float xi, float g) {
    const float th = tanh_approx(xi - g);
    return 1.0f - th * th;
}

// Two elements per thread: 1x LDG.64 in (warp = 256 B contiguous),
// 16 outputs out via 2x STG.256 (warp = 2 KB contiguous). All results
// held in named scalars: zero spill risk.
__global__ __launch_bounds__(256)
void rswaf_kernel(const float2* __restrict__ x,
                  const float4* __restrict__ grid,   // [8] floats = 2 float4
                  const float*  __restrict__ inv_den,
                  float*        __restrict__ out,
                  int n2) {
    const int i = blockIdx.x * blockDim.x + threadIdx.x;
    if (i >= n2) return;

    const float inv = __ldg(inv_den);

    // pre-scale grid by inv: (x-g)*inv = x*inv - g*inv
    const float4 gA = __ldg(grid + 0);
    const float4 gB = __ldg(grid + 1);
    const float g0 = gA.x * inv, g1 = gA.y * inv, g2 = gA.z * inv, g3 = gA.w * inv;
    const float g4 = gB.x * inv, g5 = gB.y * inv, g6 = gB.z * inv, g7 = gB.w * inv;

    const float2 xv = __ldcs(x + i);
    const float xa = xv.x * inv;
    const float xb = xv.y * inv;

    const float a0 = bump(xa, g0), a1 = bump(xa, g1), a2 = bump(xa, g2), a3 = bump(xa, g3);
    const float a4 = bump(xa, g4), a5 = bump(xa, g5), a6 = bump(xa, g6), a7 = bump(xa, g7);

    float* dst = out + (long long)i * (2 * NUM_GRIDS);
    asm volatile(
        "st.global.cs.v8.f32 [%0], {%1,%2,%3,%4,%5,%6,%7,%8};"
        :: "l"(dst),
           "f"(a0), "f"(a1), "f"(a2), "f"(a3),
           "f"(a4), "f"(a5), "f"(a6), "f"(a7)
        : "memory");

    const float b0 = bump(xb, g0), b1 = bump(xb, g1), b2 = bump(xb, g2), b3 = bump(xb, g3);
    const float b4 = bump(xb, g4), b5 = bump(xb, g5), b6 = bump(xb, g6), b7 = bump(xb, g7);

    asm volatile(
        "st.global.cs.v8.f32 [%0], {%1,%2,%3,%4,%5,%6,%7,%8};"
        :: "l"(dst + NUM_GRIDS),
           "f"(b0), "f"(b1), "f"(b2), "f"(b3),
           "f"(b4), "f"(b5), "f"(b6), "f"(b7)
        : "memory");
}

extern "C" void kernel_launch(void* const* d_in, const int* in_sizes, int n_in,
                              void* d_out, int out_size) {
    const float* x       = (const float*)d_in[0];   // [16,64,128,128] fp32
    const float* grid    = (const float*)d_in[1];   // [8] fp32
    const float* inv_den = (const float*)d_in[2];   // scalar fp32
    float* out = (float*)d_out;                     // [...,8] fp32

    const int n  = in_sizes[0];        // 16,777,216 (even)
    const int n2 = n >> 1;             // 8,388,608 float2s

    const int threads = 256;
    const int blocks  = (n2 + threads - 1) / threads;   // 32768

    rswaf_kernel<<<blocks, threads>>>(
        (const float2*)x, (const float4*)grid, inv_den, out, n2);
}